// round 1
// baseline (speedup 1.0000x reference)
#include <cuda_runtime.h>

#define NN 50000
#define NM 4
#define DD 128
#define NE 800000
#define ALPHA 0.05f
#define EPS 1e-5f

// Scratch: aggregated messages, [N, M*D] fp32 = 102.4 MB
__device__ float g_agg[(size_t)NN * NM * DD];

// ---------------------------------------------------------------------------
// Kernel 1: zero the aggregation buffer (float4 stores)
// ---------------------------------------------------------------------------
__global__ void zero_agg_kernel() {
    size_t i = (size_t)blockIdx.x * blockDim.x + threadIdx.x;
    const size_t n4 = (size_t)NN * NM * DD / 4;
    if (i < n4) {
        reinterpret_cast<float4*>(g_agg)[i] = make_float4(0.f, 0.f, 0.f, 0.f);
    }
}

// ---------------------------------------------------------------------------
// Kernel 2: edge scatter.  agg[dst] += w * x[src]  over the 512-float row.
// One thread per (edge, float4-chunk): 128 chunks per edge.
// ---------------------------------------------------------------------------
__global__ void edge_scatter_kernel(const float4* __restrict__ x4,
                                    const int* __restrict__ src,
                                    const int* __restrict__ dst,
                                    const float* __restrict__ w) {
    const int V4 = NM * DD / 4;  // 128 float4 per node row
    long long gid = (long long)blockIdx.x * blockDim.x + threadIdx.x;
    long long e = gid >> 7;       // edge index
    int d = (int)(gid & 127);     // float4 chunk within row
    if (e >= NE) return;

    int s  = __ldg(&src[e]);
    int t  = __ldg(&dst[e]);
    float we = __ldg(&w[e]);

    float4 v = x4[(long long)s * V4 + d];
    float* out = &g_agg[(((long long)t * V4 + d) << 2)];
    atomicAdd(out + 0, we * v.x);
    atomicAdd(out + 1, we * v.y);
    atomicAdd(out + 2, we * v.z);
    atomicAdd(out + 3, we * v.w);
}

// ---------------------------------------------------------------------------
// Kernel 3: per-row (node,modality) dense projection by W, residual, LayerNorm.
// One block of 128 threads per row; thread j computes output column j.
// ---------------------------------------------------------------------------
__global__ void __launch_bounds__(128) gemm_ln_kernel(
    const float* __restrict__ x,      // multimodal, [N*M, D]
    const float* __restrict__ W,      // [D, D]
    const float* __restrict__ gamma,  // [D]
    const float* __restrict__ beta,   // [D]
    float* __restrict__ out)          // [N*M, D]
{
    const int row = blockIdx.x;       // 0 .. N*M-1
    const int j = threadIdx.x;        // 0 .. 127

    __shared__ float s_agg[DD];
    __shared__ float s_sum[4], s_sq[4];

    s_agg[j] = g_agg[(size_t)row * DD + j];
    __syncthreads();

    float acc = 0.f;
#pragma unroll 16
    for (int k = 0; k < DD; k++) {
        acc = fmaf(s_agg[k], __ldg(&W[k * DD + j]), acc);
    }

    float y = __ldg(&x[(size_t)row * DD + j]) + ALPHA * acc;

    // Block reduction of sum and sum-of-squares over 128 lanes
    float s = y, ss = y * y;
#pragma unroll
    for (int o = 16; o > 0; o >>= 1) {
        s  += __shfl_xor_sync(0xFFFFFFFFu, s, o);
        ss += __shfl_xor_sync(0xFFFFFFFFu, ss, o);
    }
    int wid = j >> 5, lid = j & 31;
    if (lid == 0) { s_sum[wid] = s; s_sq[wid] = ss; }
    __syncthreads();
    s  = s_sum[0] + s_sum[1] + s_sum[2] + s_sum[3];
    ss = s_sq[0] + s_sq[1] + s_sq[2] + s_sq[3];

    const float inv_d = 1.f / (float)DD;
    float mu  = s * inv_d;
    float var = ss * inv_d - mu * mu;
    float inv = rsqrtf(var + EPS);

    out[(size_t)row * DD + j] = (y - mu) * inv * __ldg(&gamma[j]) + __ldg(&beta[j]);
}

// ---------------------------------------------------------------------------
extern "C" void kernel_launch(void* const* d_in, const int* in_sizes, int n_in,
                              void* d_out, int out_size) {
    const float* multimodal = (const float*)d_in[0];  // [N, M, D] fp32
    const int*   edge_src   = (const int*)d_in[1];    // [E]
    const int*   edge_dst   = (const int*)d_in[2];    // [E]
    const float* edge_w     = (const float*)d_in[3];  // [E]
    const float* W          = (const float*)d_in[4];  // [D, D]
    const float* gamma      = (const float*)d_in[5];  // [D]
    const float* beta       = (const float*)d_in[6];  // [D]
    float* out = (float*)d_out;

    // 1) zero agg
    {
        size_t n4 = (size_t)NN * NM * DD / 4;
        int threads = 256;
        int blocks = (int)((n4 + threads - 1) / threads);
        zero_agg_kernel<<<blocks, threads>>>();
    }
    // 2) edge scatter
    {
        long long total = (long long)NE * 128;
        int threads = 256;
        long long blocks = (total + threads - 1) / threads;
        edge_scatter_kernel<<<(unsigned int)blocks, threads>>>(
            (const float4*)multimodal, edge_src, edge_dst, edge_w);
    }
    // 3) fused GEMM + residual + LayerNorm
    {
        gemm_ln_kernel<<<NN * NM, 128>>>(multimodal, W, gamma, beta, out);
    }
}

// round 2
// speedup vs baseline: 2.6850x; 2.6850x over previous
#include <cuda_runtime.h>

#define NN 50000
#define NM 4
#define DD 128
#define NE 800000
#define ALPHA 0.05f
#define EPS 1e-5f

// ---------------------------------------------------------------------------
// CSR-by-dst scratch (device globals; no runtime allocation)
// ---------------------------------------------------------------------------
__device__ int   g_count[NN];
__device__ int   g_off[NN + 1];
__device__ int   g_cursor[NN];
__device__ int   g_src_s[NE];   // src ids sorted by dst
__device__ float g_w_s[NE];     // weights sorted by dst

// ---------------------------------------------------------------------------
// CSR build
// ---------------------------------------------------------------------------
__global__ void zero_counts_kernel() {
    int i = blockIdx.x * blockDim.x + threadIdx.x;
    if (i < NN) g_count[i] = 0;
}

__global__ void hist_kernel(const int* __restrict__ dst) {
    int e = blockIdx.x * blockDim.x + threadIdx.x;
    if (e < NE) atomicAdd(&g_count[dst[e]], 1);
}

// Single-block exclusive scan over 50K counts (Hillis-Steele per 1024 chunk,
// serial carry across chunks).
__global__ void scan_kernel() {
    __shared__ int s[1024];
    __shared__ int carry;
    if (threadIdx.x == 0) carry = 0;
    __syncthreads();
    for (int base = 0; base < NN; base += 1024) {
        int i = base + threadIdx.x;
        int v = (i < NN) ? g_count[i] : 0;
        s[threadIdx.x] = v;
        __syncthreads();
#pragma unroll
        for (int o = 1; o < 1024; o <<= 1) {
            int t = (threadIdx.x >= o) ? s[threadIdx.x - o] : 0;
            __syncthreads();
            s[threadIdx.x] += t;
            __syncthreads();
        }
        int excl = s[threadIdx.x] - v;
        if (i < NN) {
            int o = carry + excl;
            g_off[i] = o;
            g_cursor[i] = o;
        }
        __syncthreads();
        if (threadIdx.x == 0) carry += s[1023];
        __syncthreads();
    }
    if (threadIdx.x == 0) g_off[NN] = carry;
}

__global__ void fill_csr_kernel(const int* __restrict__ src,
                                const int* __restrict__ dst,
                                const float* __restrict__ w) {
    int e = blockIdx.x * blockDim.x + threadIdx.x;
    if (e < NE) {
        int t = dst[e];
        int pos = atomicAdd(&g_cursor[t], 1);
        g_src_s[pos] = src[e];
        g_w_s[pos]  = w[e];
    }
}

// ---------------------------------------------------------------------------
// Fused gather + GEMM + residual + LayerNorm.
// One CTA (128 threads) per destination node.
//   Phase 1: each thread accumulates one float4 of the 512-float agg row in
//            registers over the node's incoming edges (coalesced row reads).
//   Phase 2: agg -> smem; warp m computes modality-row m: 128-col projection
//            by W (float4 loads, 4 cols/lane), residual, warp-local LN.
// ---------------------------------------------------------------------------
__global__ void __launch_bounds__(128) fused_kernel(
    const float4* __restrict__ x4,     // multimodal as float4, row = 128 f4
    const float*  __restrict__ xf,     // multimodal flat
    const float4* __restrict__ W4,     // W as float4, row k = 32 f4
    const float4* __restrict__ gamma4, // 32 f4
    const float4* __restrict__ beta4,  // 32 f4
    float4* __restrict__ out4)         // [N*M, 32] f4
{
    const int node = blockIdx.x;
    const int tid  = threadIdx.x;

    const int begin = g_off[node];
    const int end   = g_off[node + 1];

    float4 acc = make_float4(0.f, 0.f, 0.f, 0.f);
#pragma unroll 4
    for (int e = begin; e < end; e++) {
        int   s  = g_src_s[e];
        float we = g_w_s[e];
        float4 v = x4[(size_t)s * (NM * DD / 4) + tid];
        acc.x = fmaf(we, v.x, acc.x);
        acc.y = fmaf(we, v.y, acc.y);
        acc.z = fmaf(we, v.z, acc.z);
        acc.w = fmaf(we, v.w, acc.w);
    }

    __shared__ float s_agg[NM][DD];
    reinterpret_cast<float4*>(&s_agg[0][0])[tid] = acc;
    __syncthreads();

    const int warp = tid >> 5;   // modality row 0..3
    const int lane = tid & 31;   // covers cols 4*lane .. 4*lane+3

    float a0 = 0.f, a1 = 0.f, a2 = 0.f, a3 = 0.f;
#pragma unroll 8
    for (int k = 0; k < DD; k++) {
        float  a  = s_agg[warp][k];
        float4 wv = __ldg(&W4[k * 32 + lane]);
        a0 = fmaf(a, wv.x, a0);
        a1 = fmaf(a, wv.y, a1);
        a2 = fmaf(a, wv.z, a2);
        a3 = fmaf(a, wv.w, a3);
    }

    const size_t rowg = (size_t)node * NM + warp;
    float4 xv = __ldg(reinterpret_cast<const float4*>(xf) + rowg * 32 + lane);

    float y0 = fmaf(ALPHA, a0, xv.x);
    float y1 = fmaf(ALPHA, a1, xv.y);
    float y2 = fmaf(ALPHA, a2, xv.z);
    float y3 = fmaf(ALPHA, a3, xv.w);

    // warp-level LayerNorm over the 128 columns (4 per lane)
    float s  = y0 + y1 + y2 + y3;
    float ss = y0 * y0 + y1 * y1 + y2 * y2 + y3 * y3;
#pragma unroll
    for (int o = 16; o > 0; o >>= 1) {
        s  += __shfl_xor_sync(0xFFFFFFFFu, s, o);
        ss += __shfl_xor_sync(0xFFFFFFFFu, ss, o);
    }
    const float inv_d = 1.f / (float)DD;
    float mu  = s * inv_d;
    float var = ss * inv_d - mu * mu;
    float inv = rsqrtf(var + EPS);

    float4 g = __ldg(&gamma4[lane]);
    float4 b = __ldg(&beta4[lane]);
    float4 o4;
    o4.x = fmaf((y0 - mu) * inv, g.x, b.x);
    o4.y = fmaf((y1 - mu) * inv, g.y, b.y);
    o4.z = fmaf((y2 - mu) * inv, g.z, b.z);
    o4.w = fmaf((y3 - mu) * inv, g.w, b.w);
    out4[rowg * 32 + lane] = o4;
}

// ---------------------------------------------------------------------------
extern "C" void kernel_launch(void* const* d_in, const int* in_sizes, int n_in,
                              void* d_out, int out_size) {
    const float* multimodal = (const float*)d_in[0];  // [N, M, D] fp32
    const int*   edge_src   = (const int*)d_in[1];    // [E]
    const int*   edge_dst   = (const int*)d_in[2];    // [E]
    const float* edge_w     = (const float*)d_in[3];  // [E]
    const float* W          = (const float*)d_in[4];  // [D, D]
    const float* gamma      = (const float*)d_in[5];  // [D]
    const float* beta       = (const float*)d_in[6];  // [D]
    float* out = (float*)d_out;

    zero_counts_kernel<<<(NN + 255) / 256, 256>>>();
    hist_kernel<<<(NE + 255) / 256, 256>>>(edge_dst);
    scan_kernel<<<1, 1024>>>();
    fill_csr_kernel<<<(NE + 255) / 256, 256>>>(edge_src, edge_dst, edge_w);

    fused_kernel<<<NN, 128>>>(
        (const float4*)multimodal, multimodal,
        (const float4*)W, (const float4*)gamma, (const float4*)beta,
        (float4*)out);
}